// round 8
// baseline (speedup 1.0000x reference)
#include <cuda_runtime.h>
#include <cuda_fp16.h>
#include <math.h>
#include <stdint.h>

#define NDEPTH 25
#define DT     (1.0f/25.0f)
#define NBATCH 262144
#define TILE_M 256
#define NTHREADS 512

// ---------------- smem float-index offsets ----------------
#define F_WDOWN  0            // 64x64
#define F_WDRIFT 4096         // 64x64
#define F_W1     8192         // 64x104 (padded)
#define F_NOISE  14848        // 25x64
#define F_BD     16448        // 64
#define F_BDR    16512        // 64
#define F_B1     16576        // 104
#define F_W2     16680        // 104
#define F_B2     16784        // 1 (pad 4)
#define F_BHI    16788        // 32 groups x 32 lanes x uint2 (hi frags, 8KB)
#define F_BLO    18836        // 32 groups x 32 lanes x uint2 (lo frags, 8KB)
#define F_STAGE  20884        // 256 rows x pitch 68
#define ST_PITCH 68
#define F_TOTAL  (F_STAGE + 256*ST_PITCH)
#define SMEM_BYTES (F_TOTAL*4)        // 153168 B

__device__ float g_noise[NDEPTH*64];

// ---------------- fp16 pack/split helpers ----------------
__device__ __forceinline__ uint32_t pkh(float e0, float e1) {
    uint32_t r;
    asm("cvt.rn.f16x2.f32 %0, %1, %2;" : "=r"(r) : "f"(e1), "f"(e0));
    return r;
}
__device__ __forceinline__ float h_lo(uint32_t p) {
    __half2 h = *(__half2*)&p; return __low2float(h);
}
__device__ __forceinline__ float h_hi(uint32_t p) {
    __half2 h = *(__half2*)&p; return __high2float(h);
}
__device__ __forceinline__ void split2(float v0, float v1, uint32_t& hi, uint32_t& lo) {
    hi = pkh(v0, v1);
    lo = pkh(v0 - h_lo(hi), v1 - h_hi(hi));
}

__device__ __forceinline__ void mma16816(float* c,
                                         uint32_t a0, uint32_t a1, uint32_t a2, uint32_t a3,
                                         uint32_t b0, uint32_t b1) {
    asm volatile(
        "mma.sync.aligned.m16n8k16.row.col.f32.f16.f16.f32 "
        "{%0,%1,%2,%3}, {%4,%5,%6,%7}, {%8,%9}, {%0,%1,%2,%3};"
        : "+f"(c[0]), "+f"(c[1]), "+f"(c[2]), "+f"(c[3])
        : "r"(a0), "r"(a1), "r"(a2), "r"(a3), "r"(b0), "r"(b1));
}

// ---------------- Lévy noise prologue (fp64) ----------------
__global__ void noise_kernel(const float* __restrict__ u_raw,
                             const float* __restrict__ w_raw) {
    int i = blockIdx.x * blockDim.x + threadIdx.x;
    if (i >= NDEPTH * 64) return;
    double u = (double)u_raw[i];
    double w = (double)w_raw[i];
    double U = 3.14159265358979323846 * (u - 0.5);
    double wc = w; if (wc < 1e-12) wc = 1e-12; if (wc > 1.0) wc = 1.0;
    double Wv = -log(wc); if (Wv < 1e-12) Wv = 1e-12;
    const double inv_a = 1.0 / 1.8;
    double X = (sin(1.8 * U) / pow(cos(U), inv_a))
             * pow(cos(U - 1.8 * U) / Wv, (1.0 - 1.8) * inv_a);
    double n = 0.1 * X;
    if (n >  10.0) n =  10.0;
    if (n < -10.0) n = -10.0;
    g_noise[i] = (float)n;
}

// ---------------- main: 16 warps, warp w owns rows 16w..16w+15 ----------------
__global__ void __launch_bounds__(NTHREADS, 1)
sdenet_mma(const float* __restrict__ x,
           const float* __restrict__ W_down,  const float* __restrict__ b_down,
           const float* __restrict__ W_drift, const float* __restrict__ b_drift,
           const float* __restrict__ W1,      const float* __restrict__ b1,
           const float* __restrict__ W2,      const float* __restrict__ b2,
           float* __restrict__ out) {
    extern __shared__ float sm[];
    const int tid  = threadIdx.x;
    const int wid  = tid >> 5;
    const int lane = tid & 31;
    const int quad = lane >> 2;
    const int qt   = lane & 3;

    // ---- cooperative loads ----
    for (int i = tid; i < 4096; i += NTHREADS) {
        sm[F_WDOWN  + i] = W_down[i];
        sm[F_WDRIFT + i] = W_drift[i];
    }
    for (int i = tid; i < 64 * 104; i += NTHREADS) {
        int k = i / 104, n = i % 104;
        sm[F_W1 + i] = (n < 100) ? W1[k * 100 + n] : 0.0f;
    }
    for (int i = tid; i < NDEPTH * 64; i += NTHREADS) sm[F_NOISE + i] = g_noise[i];
    if (tid < 64)  { sm[F_BD + tid] = b_down[tid]; sm[F_BDR + tid] = b_drift[tid]; }
    if (tid < 104) {
        sm[F_B1 + tid] = (tid < 100) ? b1[tid] : 0.0f;
        sm[F_W2 + tid] = (tid < 100) ? W2[tid] : 0.0f;
    }
    if (tid == 0) sm[F_B2] = b2[0];

    // x tile -> stage (coalesced)
    const float* xb = x + (size_t)blockIdx.x * (TILE_M * 64);
    for (int i = 4 * tid; i < TILE_M * 64; i += 4 * NTHREADS) {
        float4 v = *(const float4*)(xb + i);
        int r = i >> 6, c = i & 63;
        *(float4*)&sm[F_STAGE + r * ST_PITCH + c] = v;
    }
    __syncthreads();

    // ---- W_drift B-fragment tables (warp 0 builds): hi / lo, uint2 per (g,lane) ----
    // layout: group g = kt*8 + nt  (kt-major, so a kt wave reads 8 consecutive groups)
    if (wid == 0) {
#pragma unroll
        for (int nt = 0; nt < 8; nt++)
#pragma unroll
            for (int kt = 0; kt < 4; kt++) {
                int n = quad + 8 * nt;
                int k = 16 * kt + 2 * qt;
                uint32_t b0h, b0l, b1h, b1l;
                split2(sm[F_WDRIFT + k * 64 + n],       sm[F_WDRIFT + (k + 1) * 64 + n], b0h, b0l);
                split2(sm[F_WDRIFT + (k + 8) * 64 + n], sm[F_WDRIFT + (k + 9) * 64 + n], b1h, b1l);
                int g = kt * 8 + nt;
                ((uint2*)&sm[F_BHI])[g * 32 + lane] = make_uint2(b0h, b1h);
                ((uint2*)&sm[F_BLO])[g * 32 + lane] = make_uint2(b0l, b1l);
            }
    }
    __syncthreads();   // publish B tables

    const int row0 = 16 * wid + quad;

    // ---- A fragments of x (hi/lo) ----
    uint32_t ah[16], al[16];
#pragma unroll
    for (int kt = 0; kt < 4; kt++) {
        int k0 = 16 * kt + 2 * qt;
        const float* r0p = &sm[F_STAGE + row0 * ST_PITCH];
        const float* r1p = &sm[F_STAGE + (row0 + 8) * ST_PITCH];
        split2(r0p[k0],     r0p[k0 + 1], ah[4*kt + 0], al[4*kt + 0]);
        split2(r1p[k0],     r1p[k0 + 1], ah[4*kt + 1], al[4*kt + 1]);
        split2(r0p[k0 + 8], r0p[k0 + 9], ah[4*kt + 2], al[4*kt + 2]);
        split2(r1p[k0 + 8], r1p[k0 + 9], ah[4*kt + 3], al[4*kt + 3]);
    }

    // ---- GEMM1: s = x @ W_down + b_down (3-term fp16, B built on the fly) ----
    float d[8][4];
#pragma unroll
    for (int nt = 0; nt < 8; nt++) {
        int c0 = 8 * nt + 2 * qt;
        float c[4] = { sm[F_BD + c0], sm[F_BD + c0 + 1], sm[F_BD + c0], sm[F_BD + c0 + 1] };
        int n = quad + 8 * nt;
#pragma unroll
        for (int kt = 0; kt < 4; kt++) {
            int k = 16 * kt + 2 * qt;
            uint32_t b0h, b0l, b1h, b1l;
            split2(sm[F_WDOWN + k * 64 + n],       sm[F_WDOWN + (k + 1) * 64 + n], b0h, b0l);
            split2(sm[F_WDOWN + (k + 8) * 64 + n], sm[F_WDOWN + (k + 9) * 64 + n], b1h, b1l);
            mma16816(c, ah[4*kt], ah[4*kt+1], ah[4*kt+2], ah[4*kt+3], b0h, b1h);
            mma16816(c, al[4*kt], al[4*kt+1], al[4*kt+2], al[4*kt+3], b0h, b1h);
            mma16816(c, ah[4*kt], ah[4*kt+1], ah[4*kt+2], ah[4*kt+3], b0l, b1l);
        }
        d[nt][0] = c[0]; d[nt][1] = c[1]; d[nt][2] = c[2]; d[nt][3] = c[3];
    }

    // rebuild A fragments from state (full split for MLP precision)
#pragma unroll
    for (int kt = 0; kt < 4; kt++) {
        split2(d[2*kt][0],   d[2*kt][1],   ah[4*kt + 0], al[4*kt + 0]);
        split2(d[2*kt][2],   d[2*kt][3],   ah[4*kt + 1], al[4*kt + 1]);
        split2(d[2*kt+1][0], d[2*kt+1][1], ah[4*kt + 2], al[4*kt + 2]);
        split2(d[2*kt+1][2], d[2*kt+1][3], ah[4*kt + 3], al[4*kt + 3]);
    }

    // ---- diffusion MLP (3-term fp16) ----
    float p0 = 0.0f, p1 = 0.0f;
#pragma unroll
    for (int nt = 0; nt < 13; nt++) {
        float c[4] = {0.f, 0.f, 0.f, 0.f};
        int n = quad + 8 * nt;
#pragma unroll
        for (int kt = 0; kt < 4; kt++) {
            int k = 16 * kt + 2 * qt;
            uint32_t b0h, b0l, b1h, b1l;
            split2(sm[F_W1 + k * 104 + n],       sm[F_W1 + (k + 1) * 104 + n], b0h, b0l);
            split2(sm[F_W1 + (k + 8) * 104 + n], sm[F_W1 + (k + 9) * 104 + n], b1h, b1l);
            mma16816(c, ah[4*kt], ah[4*kt+1], ah[4*kt+2], ah[4*kt+3], b0h, b1h);
            mma16816(c, al[4*kt], al[4*kt+1], al[4*kt+2], al[4*kt+3], b0h, b1h);
            mma16816(c, ah[4*kt], ah[4*kt+1], ah[4*kt+2], ah[4*kt+3], b0l, b1l);
        }
        int c0 = 8 * nt + 2 * qt;
        float w20 = sm[F_W2 + c0], w21 = sm[F_W2 + c0 + 1];
        float bb0 = sm[F_B1 + c0], bb1 = sm[F_B1 + c0 + 1];
        p0 += fmaxf(c[0] + bb0, 0.f) * w20 + fmaxf(c[1] + bb1, 0.f) * w21;
        p1 += fmaxf(c[2] + bb0, 0.f) * w20 + fmaxf(c[3] + bb1, 0.f) * w21;
    }
    p0 += __shfl_xor_sync(0xffffffffu, p0, 1);
    p0 += __shfl_xor_sync(0xffffffffu, p0, 2);
    p1 += __shfl_xor_sync(0xffffffffu, p1, 1);
    p1 += __shfl_xor_sync(0xffffffffu, p1, 2);
    const float dtpow = powf(DT, 1.0f / 1.8f);
    const float b2v = sm[F_B2];
    const float scale0 = 0.5f * dtpow / (1.0f + expf(-(p0 + b2v)));
    const float scale1 = 0.5f * dtpow / (1.0f + expf(-(p1 + b2v)));

    // ---- 25 drift steps: single-term A-hi x B-hi, kt-OUTER for ILP ----
    // Dependent MMAs on the same c[nt] are spaced 8 independent MMAs apart;
    // each kt wave's 8 B-loads are issued as a group ahead of its MMAs.
    const uint2* tbh = (const uint2*)&sm[F_BHI] + lane;
    const uint2* tbl = (const uint2*)&sm[F_BLO] + lane;
    const float* bdrp = &sm[F_BDR + 2 * qt];
    const float* nzp  = &sm[F_NOISE + 2 * qt];
#pragma unroll 1
    for (int st = 0; st < NDEPTH; st++) {
        // init accumulators from drift bias (smem, broadcast)
        float c[8][4];
#pragma unroll
        for (int nt = 0; nt < 8; nt++) {
            float2 bb = *(const float2*)(bdrp + 8 * nt);
            c[nt][0] = bb.x; c[nt][1] = bb.y; c[nt][2] = bb.x; c[nt][3] = bb.y;
        }
        // 4 kt waves; within a wave all 8 MMAs are independent
#pragma unroll
        for (int kt = 0; kt < 4; kt++) {
            uint2 b[8];
#pragma unroll
            for (int nt = 0; nt < 8; nt++) b[nt] = tbh[(kt * 8 + nt) * 32];
#pragma unroll
            for (int nt = 0; nt < 8; nt++)
                mma16816(c[nt], ah[4*kt], ah[4*kt+1], ah[4*kt+2], ah[4*kt+3],
                         b[nt].x, b[nt].y);
        }
        // elementwise update + A-hi rebuild
        const float* nz = nzp + st * 64;
#pragma unroll
        for (int nt = 0; nt < 8; nt++) {
            float2 z = *(const float2*)(nz + 8 * nt);
            float sn00 = scale0 * z.x, sn01 = scale0 * z.y;
            float sn10 = scale1 * z.x, sn11 = scale1 * z.y;
            // d = d*(1+dt) + relu(c)*dt + scale*noise
            d[nt][0] = fmaf(d[nt][0], 1.0f + DT, fmaf(fmaxf(c[nt][0], 0.f), DT, sn00));
            d[nt][1] = fmaf(d[nt][1], 1.0f + DT, fmaf(fmaxf(c[nt][1], 0.f), DT, sn01));
            d[nt][2] = fmaf(d[nt][2], 1.0f + DT, fmaf(fmaxf(c[nt][2], 0.f), DT, sn10));
            d[nt][3] = fmaf(d[nt][3], 1.0f + DT, fmaf(fmaxf(c[nt][3], 0.f), DT, sn11));
        }
#pragma unroll
        for (int kt = 0; kt < 4; kt++) {
            ah[4*kt + 0] = pkh(d[2*kt][0],   d[2*kt][1]);
            ah[4*kt + 1] = pkh(d[2*kt][2],   d[2*kt][3]);
            ah[4*kt + 2] = pkh(d[2*kt+1][0], d[2*kt+1][1]);
            ah[4*kt + 3] = pkh(d[2*kt+1][2], d[2*kt+1][3]);
        }
    }

    // ---- final drift_out GEMM: full precision (3-term, A fully split) ----
#pragma unroll
    for (int kt = 0; kt < 4; kt++) {
        split2(d[2*kt][0],   d[2*kt][1],   ah[4*kt + 0], al[4*kt + 0]);
        split2(d[2*kt][2],   d[2*kt][3],   ah[4*kt + 1], al[4*kt + 1]);
        split2(d[2*kt+1][0], d[2*kt+1][1], ah[4*kt + 2], al[4*kt + 2]);
        split2(d[2*kt+1][2], d[2*kt+1][3], ah[4*kt + 3], al[4*kt + 3]);
    }
#pragma unroll
    for (int nt = 0; nt < 8; nt++) {
        int c0 = 8 * nt + 2 * qt;
        float2 bb = *(const float2*)&sm[F_BDR + c0];
        float c[4] = { bb.x, bb.y, bb.x, bb.y };
#pragma unroll
        for (int kt = 0; kt < 4; kt++) {
            uint2 b = tbh[(kt * 8 + nt) * 32];
            uint2 l = tbl[(kt * 8 + nt) * 32];
            mma16816(c, ah[4*kt], ah[4*kt+1], ah[4*kt+2], ah[4*kt+3], b.x, b.y);
            mma16816(c, al[4*kt], al[4*kt+1], al[4*kt+2], al[4*kt+3], b.x, b.y);
            mma16816(c, ah[4*kt], ah[4*kt+1], ah[4*kt+2], ah[4*kt+3], l.x, l.y);
        }
        sm[F_STAGE + row0 * ST_PITCH + c0]           = fmaxf(c[0], 0.f) + d[nt][0];
        sm[F_STAGE + row0 * ST_PITCH + c0 + 1]       = fmaxf(c[1], 0.f) + d[nt][1];
        sm[F_STAGE + (row0 + 8) * ST_PITCH + c0]     = fmaxf(c[2], 0.f) + d[nt][2];
        sm[F_STAGE + (row0 + 8) * ST_PITCH + c0 + 1] = fmaxf(c[3], 0.f) + d[nt][3];
    }

    // ---- write drift_out (coalesced via stage) ----
    __syncthreads();
    float* o0 = out + (size_t)blockIdx.x * (TILE_M * 64);
    for (int i = 4 * tid; i < TILE_M * 64; i += 4 * NTHREADS) {
        int r = i >> 6, c = i & 63;
        *(float4*)(o0 + i) = *(const float4*)&sm[F_STAGE + r * ST_PITCH + c];
    }
    __syncthreads();

    // ---- stage + write final state ----
#pragma unroll
    for (int nt = 0; nt < 8; nt++) {
        int c0 = 8 * nt + 2 * qt;
        sm[F_STAGE + row0 * ST_PITCH + c0]           = d[nt][0];
        sm[F_STAGE + row0 * ST_PITCH + c0 + 1]       = d[nt][1];
        sm[F_STAGE + (row0 + 8) * ST_PITCH + c0]     = d[nt][2];
        sm[F_STAGE + (row0 + 8) * ST_PITCH + c0 + 1] = d[nt][3];
    }
    __syncthreads();
    float* o1 = out + (size_t)NBATCH * 64 + (size_t)blockIdx.x * (TILE_M * 64);
    for (int i = 4 * tid; i < TILE_M * 64; i += 4 * NTHREADS) {
        int r = i >> 6, c = i & 63;
        *(float4*)(o1 + i) = *(const float4*)&sm[F_STAGE + r * ST_PITCH + c];
    }
}

extern "C" void kernel_launch(void* const* d_in, const int* in_sizes, int n_in,
                              void* d_out, int out_size) {
    const float* x       = (const float*)d_in[0];
    const float* u_raw   = (const float*)d_in[1];
    const float* w_raw   = (const float*)d_in[2];
    const float* W_down  = (const float*)d_in[3];
    const float* b_down  = (const float*)d_in[4];
    const float* W_drift = (const float*)d_in[5];
    const float* b_drift = (const float*)d_in[6];
    const float* W1      = (const float*)d_in[7];
    const float* b1      = (const float*)d_in[8];
    const float* W2      = (const float*)d_in[9];
    const float* b2      = (const float*)d_in[10];
    float* out = (float*)d_out;

    noise_kernel<<<(NDEPTH * 64 + 255) / 256, 256>>>(u_raw, w_raw);

    cudaFuncSetAttribute(sdenet_mma,
                         cudaFuncAttributeMaxDynamicSharedMemorySize, SMEM_BYTES);
    sdenet_mma<<<NBATCH / TILE_M, NTHREADS, SMEM_BYTES>>>(
        x, W_down, b_down, W_drift, b_drift, W1, b1, W2, b2, out);
}